// round 1
// baseline (speedup 1.0000x reference)
#include <cuda_runtime.h>

#define HH 128
#define WW 128
#define HWSZ (128*128)
#define CIN 64
#define COUT 64
#define BATCH 8

// scratch (__device__ globals: allocation-free)
__device__ float g_off[BATCH * 27 * HWSZ];     // [b][27][H][W]: dy0,dx0,..,dy8,dx8, m0..m8
__device__ float g_wpack[576 * COUT];          // [(c*9+kk)][oc]
__device__ float g_opack[576 * 28];            // [(c*9+kk)][o] o<18 offset_w, 18..26 mod_w, 27 pad

// ---- packed f32x2 helpers (Blackwell FFMA2 path) ----
static __device__ __forceinline__ unsigned long long pk2(float lo, float hi) {
    unsigned long long r;
    asm("mov.b64 %0, {%1,%2};" : "=l"(r) : "f"(lo), "f"(hi));
    return r;
}
static __device__ __forceinline__ void fma2(unsigned long long& d,
                                            unsigned long long a,
                                            unsigned long long b) {
    asm("fma.rn.f32x2 %0, %1, %2, %0;" : "+l"(d) : "l"(a), "l"(b));
}
static __device__ __forceinline__ float2 unpk2(unsigned long long v) {
    float2 f;
    asm("mov.b64 {%0,%1}, %2;" : "=f"(f.x), "=f"(f.y) : "l"(v));
    return f;
}

// ---- prep: repack weights so oc (or o) is contiguous per (c,kk) row ----
__global__ void prep_kernel(const float* __restrict__ weight,
                            const float* __restrict__ ow,
                            const float* __restrict__ mw) {
    int i = blockIdx.x * blockDim.x + threadIdx.x;
    if (i < 576 * COUT) {
        int ck = i >> 6;
        int oc = i & 63;
        g_wpack[i] = weight[oc * 576 + ck];
    }
    if (i < 576 * 28) {
        int ck = i / 28;
        int o = i - ck * 28;
        float v = 0.f;
        if (o < 18)      v = ow[o * 576 + ck];
        else if (o < 27) v = mw[(o - 18) * 576 + ck];
        g_opack[i] = v;
    }
}

// ---- kernel 1: fused offset+modulator 3x3 conv (27 outputs), tile 32x8 ----
__global__ __launch_bounds__(128) void conv_om_kernel(const float* __restrict__ x,
                                                      const float* __restrict__ ob,
                                                      const float* __restrict__ mb) {
    __shared__ float owS[144 * 28];   // 16 channels worth of packed weights (16128 B)
    __shared__ float sxt[4 * 340];    // 4-channel input tile, 10x34 each (5440 B)

    int tid = threadIdx.x;
    int tx = tid & 31;
    int tyq = tid >> 5;                 // 0..3; each thread handles rows tyq and tyq+4
    int tw0 = blockIdx.x * 32;
    int th0 = blockIdx.y * 8;
    int b = blockIdx.z;
    const float* xb = x + (size_t)b * CIN * HWSZ;

    unsigned long long acc0[14], acc1[14];
#pragma unroll
    for (int p = 0; p < 14; p++) { acc0[p] = 0ull; acc1[p] = 0ull; }

    for (int cc = 0; cc < 4; cc++) {
        __syncthreads();
        for (int i = tid; i < 144 * 28; i += 128)
            owS[i] = g_opack[cc * 144 * 28 + i];

        for (int cb = 0; cb < 4; cb++) {
            __syncthreads();
            int cbase = cc * 16 + cb * 4;
            for (int i = tid; i < 4 * 340; i += 128) {
                int c = cbase + i / 340;
                int rem = i % 340;
                int r = rem / 34;
                int cl2 = rem - r * 34;
                int gy = th0 - 1 + r;
                int gx = tw0 - 1 + cl2;
                float v = 0.f;
                if ((unsigned)gy < HH && (unsigned)gx < WW)
                    v = xb[c * HWSZ + gy * WW + gx];
                sxt[i] = v;
            }
            __syncthreads();
#pragma unroll 1
            for (int j = 0; j < 4; j++) {
                const float* s0 = &sxt[j * 340 + tyq * 34 + tx];
                int rowbase = ((cb * 4 + j) * 9) * 28;
#pragma unroll
                for (int kk = 0; kk < 9; kk++) {
                    const int ki = kk / 3, kj = kk % 3;
                    float xv0 = s0[ki * 34 + kj];
                    float xv1 = s0[(ki + 4) * 34 + kj];
                    const unsigned long long* wr =
                        (const unsigned long long*)&owS[rowbase + kk * 28];
                    unsigned long long v0 = pk2(xv0, xv0);
                    unsigned long long v1 = pk2(xv1, xv1);
#pragma unroll
                    for (int p = 0; p < 14; p++) {
                        unsigned long long w2 = wr[p];
                        fma2(acc0[p], v0, w2);
                        fma2(acc1[p], v1, w2);
                    }
                }
            }
        }
    }

    int y0 = th0 + tyq;
    int y1 = th0 + tyq + 4;
    int xo = tw0 + tx;
    float vals0[28], vals1[28];
#pragma unroll
    for (int p = 0; p < 14; p++) {
        float2 f0 = unpk2(acc0[p]), f1 = unpk2(acc1[p]);
        vals0[2 * p] = f0.x; vals0[2 * p + 1] = f0.y;
        vals1[2 * p] = f1.x; vals1[2 * p + 1] = f1.y;
    }
#pragma unroll
    for (int o = 0; o < 27; o++) {
        float v0 = vals0[o], v1 = vals1[o];
        if (o < 18) {
            float bb = ob[o];
            v0 += bb; v1 += bb;
        } else {
            float bb = mb[o - 18];
            v0 = 2.f / (1.f + __expf(-(v0 + bb)));
            v1 = 2.f / (1.f + __expf(-(v1 + bb)));
        }
        float* dst = &g_off[((size_t)b * 27 + o) * HWSZ];
        dst[y0 * WW + xo] = v0;
        dst[y1 * WW + xo] = v1;
    }
}

// ---- kernel 2: deformable gather + 64-wide GEMM, 1 thread = 1 position ----
__global__ __launch_bounds__(128) void deform_kernel(const float* __restrict__ x,
                                                     float* __restrict__ out) {
    __shared__ float wS[16 * 9 * 64];  // 36864 B: weights for 16 input channels

    int wo = threadIdx.x;
    int ho = blockIdx.x;
    int b = blockIdx.y;
    const float* xb = x + (size_t)b * CIN * HWSZ;
    const float* offb = g_off + (size_t)b * 27 * HWSZ;
    int pos = ho * WW + wo;

    unsigned long long acc[32];
#pragma unroll
    for (int p = 0; p < 32; p++) acc[p] = 0ull;

    for (int cc = 0; cc < 4; cc++) {
        __syncthreads();
        for (int i = threadIdx.x; i < 16 * 9 * 64; i += 128)
            wS[i] = g_wpack[cc * (16 * 9 * 64) + i];
        __syncthreads();

#pragma unroll 1
        for (int kk = 0; kk < 9; kk++) {
            int ki = kk / 3, kj = kk - ki * 3;
            float dy = offb[(kk * 2) * HWSZ + pos];
            float dx = offb[(kk * 2 + 1) * HWSZ + pos];
            float m  = offb[(18 + kk) * HWSZ + pos];
            float fy = (float)(ho - 1 + ki) + dy;
            float fx = (float)(wo - 1 + kj) + dx;
            float fy0 = floorf(fy), fx0 = floorf(fx);
            int iy0 = (int)fy0, ix0 = (int)fx0;
            float wy = fy - fy0, wx = fx - fx0;
            bool vy0 = (unsigned)iy0 < HH;
            bool vy1 = (unsigned)(iy0 + 1) < HH;
            bool vx0 = (unsigned)ix0 < WW;
            bool vx1 = (unsigned)(ix0 + 1) < WW;
            float a00 = (1.f - wy) * (1.f - wx) * m * ((vy0 && vx0) ? 1.f : 0.f);
            float a01 = (1.f - wy) * wx         * m * ((vy0 && vx1) ? 1.f : 0.f);
            float a10 = wy * (1.f - wx)         * m * ((vy1 && vx0) ? 1.f : 0.f);
            float a11 = wy * wx                 * m * ((vy1 && vx1) ? 1.f : 0.f);
            int cy0 = min(max(iy0, 0), HH - 1);
            int cy1 = min(max(iy0 + 1, 0), HH - 1);
            int cx0 = min(max(ix0, 0), WW - 1);
            int cx1 = min(max(ix0 + 1, 0), WW - 1);
            int o00 = cy0 * WW + cx0, o01 = cy0 * WW + cx1;
            int o10 = cy1 * WW + cx0, o11 = cy1 * WW + cx1;

            const float* xc = xb + cc * 16 * HWSZ;
#pragma unroll 4
            for (int cl = 0; cl < 16; cl++) {
                const float* p = xc + cl * HWSZ;
                float v = a00 * __ldg(p + o00) + a01 * __ldg(p + o01)
                        + a10 * __ldg(p + o10) + a11 * __ldg(p + o11);
                unsigned long long vv = pk2(v, v);
                const ulonglong2* wr = (const ulonglong2*)&wS[(cl * 9 + kk) * 64];
#pragma unroll
                for (int q = 0; q < 16; q++) {
                    ulonglong2 w4 = wr[q];
                    fma2(acc[2 * q],     vv, w4.x);
                    fma2(acc[2 * q + 1], vv, w4.y);
                }
            }
        }
    }

    float* ob = out + (size_t)b * COUT * HWSZ;
#pragma unroll
    for (int p = 0; p < 32; p++) {
        float2 f = unpk2(acc[p]);
        ob[(2 * p) * HWSZ + pos] = f.x;
        ob[(2 * p + 1) * HWSZ + pos] = f.y;
    }
}

extern "C" void kernel_launch(void* const* d_in, const int* in_sizes, int n_in,
                              void* d_out, int out_size) {
    const float* x  = (const float*)d_in[0];  // [8,64,128,128]
    const float* ow = (const float*)d_in[1];  // [18,64,3,3]
    const float* ob = (const float*)d_in[2];  // [18]
    const float* mw = (const float*)d_in[3];  // [9,64,3,3]
    const float* mb = (const float*)d_in[4];  // [9]
    const float* wt = (const float*)d_in[5];  // [64,64,3,3]
    float* out = (float*)d_out;               // [8,64,128,128]

    prep_kernel<<<144, 256>>>(wt, ow, mw);

    dim3 g1(WW / 32, HH / 8, BATCH);
    conv_om_kernel<<<g1, 128>>>(x, ob, mb);

    dim3 g2(HH, BATCH);
    deform_kernel<<<g2, 128>>>(x, out);
}

// round 2
// speedup vs baseline: 1.0328x; 1.0328x over previous
#include <cuda_runtime.h>

#define HH 128
#define WW 128
#define HWSZ (128*128)
#define CIN 64
#define COUT 64
#define BATCH 8

// scratch (__device__ globals: allocation-free)
__device__ float g_off[BATCH * 27 * HWSZ];     // [b][27][H][W]: dy0,dx0,..,dy8,dx8, m0..m8
__device__ float g_wpack[576 * COUT];          // [(c*9+kk)][oc]
__device__ float g_opack[576 * 28];            // [(c*9+kk)][o] o<18 offset_w, 18..26 mod_w, 27 pad

// ---- packed f32x2 helpers (Blackwell FFMA2 path) ----
static __device__ __forceinline__ unsigned long long pk2(float lo, float hi) {
    unsigned long long r;
    asm("mov.b64 %0, {%1,%2};" : "=l"(r) : "f"(lo), "f"(hi));
    return r;
}
static __device__ __forceinline__ void fma2(unsigned long long& d,
                                            unsigned long long a,
                                            unsigned long long b) {
    asm("fma.rn.f32x2 %0, %1, %2, %0;" : "+l"(d) : "l"(a), "l"(b));
}
static __device__ __forceinline__ float2 unpk2(unsigned long long v) {
    float2 f;
    asm("mov.b64 {%0,%1}, %2;" : "=f"(f.x), "=f"(f.y) : "l"(v));
    return f;
}

// ---- prep: repack weights so oc (or o) is contiguous per (c,kk) row ----
__global__ void prep_kernel(const float* __restrict__ weight,
                            const float* __restrict__ ow,
                            const float* __restrict__ mw) {
    int i = blockIdx.x * blockDim.x + threadIdx.x;
    if (i < 576 * COUT) {
        int ck = i >> 6;
        int oc = i & 63;
        g_wpack[i] = weight[oc * 576 + ck];
    }
    if (i < 576 * 28) {
        int ck = i / 28;
        int o = i - ck * 28;
        float v = 0.f;
        if (o < 18)      v = ow[o * 576 + ck];
        else if (o < 27) v = mw[(o - 18) * 576 + ck];
        g_opack[i] = v;
    }
}

// ---- kernel 1: fused offset+modulator 3x3 conv (27 outputs), tile 32x8 ----
__global__ __launch_bounds__(128) void conv_om_kernel(const float* __restrict__ x,
                                                      const float* __restrict__ ob,
                                                      const float* __restrict__ mb) {
    __shared__ float owS[144 * 28];   // 16 channels worth of packed weights (16128 B)
    __shared__ float sxt[4 * 340];    // 4-channel input tile, 10x34 each (5440 B)

    int tid = threadIdx.x;
    int tx = tid & 31;
    int tyq = tid >> 5;                 // 0..3; each thread handles rows tyq and tyq+4
    int tw0 = blockIdx.x * 32;
    int th0 = blockIdx.y * 8;
    int b = blockIdx.z;
    const float* xb = x + (size_t)b * CIN * HWSZ;

    unsigned long long acc0[14], acc1[14];
#pragma unroll
    for (int p = 0; p < 14; p++) { acc0[p] = 0ull; acc1[p] = 0ull; }

    for (int cc = 0; cc < 4; cc++) {
        __syncthreads();
        for (int i = tid; i < 144 * 28; i += 128)
            owS[i] = g_opack[cc * 144 * 28 + i];

        for (int cb = 0; cb < 4; cb++) {
            __syncthreads();
            int cbase = cc * 16 + cb * 4;
            for (int i = tid; i < 4 * 340; i += 128) {
                int c = cbase + i / 340;
                int rem = i % 340;
                int r = rem / 34;
                int cl2 = rem - r * 34;
                int gy = th0 - 1 + r;
                int gx = tw0 - 1 + cl2;
                float v = 0.f;
                if ((unsigned)gy < HH && (unsigned)gx < WW)
                    v = xb[c * HWSZ + gy * WW + gx];
                sxt[i] = v;
            }
            __syncthreads();
#pragma unroll 1
            for (int j = 0; j < 4; j++) {
                const float* s0 = &sxt[j * 340 + tyq * 34 + tx];
                int rowbase = ((cb * 4 + j) * 9) * 28;
#pragma unroll
                for (int kk = 0; kk < 9; kk++) {
                    const int ki = kk / 3, kj = kk % 3;
                    float xv0 = s0[ki * 34 + kj];
                    float xv1 = s0[(ki + 4) * 34 + kj];
                    const unsigned long long* wr =
                        (const unsigned long long*)&owS[rowbase + kk * 28];
                    unsigned long long v0 = pk2(xv0, xv0);
                    unsigned long long v1 = pk2(xv1, xv1);
#pragma unroll
                    for (int p = 0; p < 14; p++) {
                        unsigned long long w2 = wr[p];
                        fma2(acc0[p], v0, w2);
                        fma2(acc1[p], v1, w2);
                    }
                }
            }
        }
    }

    int y0 = th0 + tyq;
    int y1 = th0 + tyq + 4;
    int xo = tw0 + tx;
    float vals0[28], vals1[28];
#pragma unroll
    for (int p = 0; p < 14; p++) {
        float2 f0 = unpk2(acc0[p]), f1 = unpk2(acc1[p]);
        vals0[2 * p] = f0.x; vals0[2 * p + 1] = f0.y;
        vals1[2 * p] = f1.x; vals1[2 * p + 1] = f1.y;
    }
#pragma unroll
    for (int o = 0; o < 27; o++) {
        float v0 = vals0[o], v1 = vals1[o];
        if (o < 18) {
            float bb = ob[o];
            v0 += bb; v1 += bb;
        } else {
            float bb = mb[o - 18];
            v0 = 2.f / (1.f + __expf(-(v0 + bb)));
            v1 = 2.f / (1.f + __expf(-(v1 + bb)));
        }
        float* dst = &g_off[((size_t)b * 27 + o) * HWSZ];
        dst[y0 * WW + xo] = v0;
        dst[y1 * WW + xo] = v1;
    }
}

// ---- kernel 2: deformable gather + 64-wide GEMM, 1 thread = 1 position ----
__global__ __launch_bounds__(128) void deform_kernel(const float* __restrict__ x,
                                                     float* __restrict__ out) {
    __shared__ float wS[16 * 9 * 64];  // 36864 B: weights for 16 input channels

    int wo = threadIdx.x;
    int ho = blockIdx.x;
    int b = blockIdx.y;
    const float* xb = x + (size_t)b * CIN * HWSZ;
    const float* offb = g_off + (size_t)b * 27 * HWSZ;
    int pos = ho * WW + wo;

    unsigned long long acc[32];
#pragma unroll
    for (int p = 0; p < 32; p++) acc[p] = 0ull;

    for (int cc = 0; cc < 4; cc++) {
        __syncthreads();
        for (int i = threadIdx.x; i < 16 * 9 * 64; i += 128)
            wS[i] = g_wpack[cc * (16 * 9 * 64) + i];
        __syncthreads();

#pragma unroll 1
        for (int kk = 0; kk < 9; kk++) {
            int ki = kk / 3, kj = kk - ki * 3;
            float dy = offb[(kk * 2) * HWSZ + pos];
            float dx = offb[(kk * 2 + 1) * HWSZ + pos];
            float m  = offb[(18 + kk) * HWSZ + pos];
            float fy = (float)(ho - 1 + ki) + dy;
            float fx = (float)(wo - 1 + kj) + dx;
            float fy0 = floorf(fy), fx0 = floorf(fx);
            int iy0 = (int)fy0, ix0 = (int)fx0;
            float wy = fy - fy0, wx = fx - fx0;
            bool vy0 = (unsigned)iy0 < HH;
            bool vy1 = (unsigned)(iy0 + 1) < HH;
            bool vx0 = (unsigned)ix0 < WW;
            bool vx1 = (unsigned)(ix0 + 1) < WW;
            float a00 = (1.f - wy) * (1.f - wx) * m * ((vy0 && vx0) ? 1.f : 0.f);
            float a01 = (1.f - wy) * wx         * m * ((vy0 && vx1) ? 1.f : 0.f);
            float a10 = wy * (1.f - wx)         * m * ((vy1 && vx0) ? 1.f : 0.f);
            float a11 = wy * wx                 * m * ((vy1 && vx1) ? 1.f : 0.f);
            int cy0 = min(max(iy0, 0), HH - 1);
            int cy1 = min(max(iy0 + 1, 0), HH - 1);
            int cx0 = min(max(ix0, 0), WW - 1);
            int cx1 = min(max(ix0 + 1, 0), WW - 1);
            int o00 = cy0 * WW + cx0, o01 = cy0 * WW + cx1;
            int o10 = cy1 * WW + cx0, o11 = cy1 * WW + cx1;

            const float* xc = xb + cc * 16 * HWSZ;
#pragma unroll 4
            for (int cl = 0; cl < 16; cl++) {
                const float* p = xc + cl * HWSZ;
                float v = a00 * __ldg(p + o00) + a01 * __ldg(p + o01)
                        + a10 * __ldg(p + o10) + a11 * __ldg(p + o11);
                unsigned long long vv = pk2(v, v);
                const ulonglong2* wr = (const ulonglong2*)&wS[(cl * 9 + kk) * 64];
#pragma unroll
                for (int q = 0; q < 16; q++) {
                    ulonglong2 w4 = wr[q];
                    fma2(acc[2 * q],     vv, w4.x);
                    fma2(acc[2 * q + 1], vv, w4.y);
                }
            }
        }
    }

    float* ob = out + (size_t)b * COUT * HWSZ;
#pragma unroll
    for (int p = 0; p < 32; p++) {
        float2 f = unpk2(acc[p]);
        ob[(2 * p) * HWSZ + pos] = f.x;
        ob[(2 * p + 1) * HWSZ + pos] = f.y;
    }
}

extern "C" void kernel_launch(void* const* d_in, const int* in_sizes, int n_in,
                              void* d_out, int out_size) {
    const float* x  = (const float*)d_in[0];  // [8,64,128,128]
    const float* ow = (const float*)d_in[1];  // [18,64,3,3]
    const float* ob = (const float*)d_in[2];  // [18]
    const float* mw = (const float*)d_in[3];  // [9,64,3,3]
    const float* mb = (const float*)d_in[4];  // [9]
    const float* wt = (const float*)d_in[5];  // [64,64,3,3]
    float* out = (float*)d_out;               // [8,64,128,128]

    prep_kernel<<<144, 256>>>(wt, ow, mw);

    dim3 g1(WW / 32, HH / 8, BATCH);
    conv_om_kernel<<<g1, 128>>>(x, ob, mb);

    dim3 g2(HH, BATCH);
    deform_kernel<<<g2, 128>>>(x, out);
}